// round 13
// baseline (speedup 1.0000x reference)
#include <cuda_runtime.h>
#include <cuda_fp16.h>
#include <cstdint>
#include <math.h>

#define BB 8
#define NN 2048
#define DD 128
#define KK 64
#define TT 32
#define TILES 64   // NN / TT

// per-tile partials (fully rewritten every launch -> no zero kernel)
__device__ float g_Pp[BB * TILES * KK * DD];   // 16 MB (L2-resident)
__device__ float g_sp[BB * TILES * KK];
__device__ unsigned int g_arr[BB];
__device__ unsigned int g_dep[BB];
__device__ half  g_Ch[KK * DD];                // fp16 centroids (prep kernel)
__device__ float g_cn2[KK];                    // ||c_k||^2 from rounded halves

// half strides: Cs/xs rows = 136 halves; At rows = 40 halves
#define STRC 136
#define STRA 40

// smem byte offsets
#define O_CS   0                       // 64*136*2 = 17408
#define O_XS   17408                   // 32*136*2 = 8704
#define O_AT   26112                   // 64*40*2  = 5120
#define O_CN2  31232                   // 64 floats
#define O_SSM  31488                   // 64 floats
#define O_RED  31744                   // 16 floats
#define SMEMB  31808

// ---- FFMA-only transcendentals (avoid the 0.5 op/cyc/SM MUFU pipe) ----
__device__ __forceinline__ float fexp(float x) {      // e^x, |x| small here
    float y = x * 1.4426950408889634f;
    float t = y + 12582912.f;                          // round-to-nearest int
    int j = __float_as_int(t) << 23;
    float f = y - (t - 12582912.f);                    // frac in [-0.5, 0.5]
    float p = 1.3333558e-3f;
    p = fmaf(p, f, 9.6181291e-3f);
    p = fmaf(p, f, 5.5504109e-2f);
    p = fmaf(p, f, 2.4022648e-1f);
    p = fmaf(p, f, 6.9314718e-1f);
    p = fmaf(p, f, 1.0f);
    return __int_as_float(__float_as_int(p) + j);
}
__device__ __forceinline__ float frsqrt(float s) {    // 1/sqrt(s), s > 0
    float h = __int_as_float(0x5f375a86 - (__float_as_int(s) >> 1));
    h = h * fmaf(-0.5f * s, h * h, 1.5f);
    h = h * fmaf(-0.5f * s, h * h, 1.5f);
    return h;
}
__device__ __forceinline__ float frcp(float s) {      // 1/s, s > 0
    float r = __int_as_float(0x7ef311c3 - __float_as_int(s));
    r = r * fmaf(-s, r, 2.0f);
    r = r * fmaf(-s, r, 2.0f);
    return r;
}

__device__ __forceinline__ void mma16(float* d, const uint32_t* a, const uint32_t* b) {
    asm volatile(
        "mma.sync.aligned.m16n8k16.row.col.f32.f16.f16.f32 "
        "{%0,%1,%2,%3}, {%4,%5,%6,%7}, {%8,%9}, {%0,%1,%2,%3};"
        : "+f"(d[0]), "+f"(d[1]), "+f"(d[2]), "+f"(d[3])
        : "r"(a[0]), "r"(a[1]), "r"(a[2]), "r"(a[3]), "r"(b[0]), "r"(b[1]));
}
#define LDSM4(r, addr) \
    asm volatile("ldmatrix.sync.aligned.m8n8.x4.shared.b16 {%0,%1,%2,%3}, [%4];" \
        : "=r"((r)[0]), "=r"((r)[1]), "=r"((r)[2]), "=r"((r)[3]) : "r"(addr))

// ---------------------------------------------------------------------------
// prep: convert C to fp16 + cn2 from rounded halves. 1 block, 256 threads.
// ---------------------------------------------------------------------------
__global__ void __launch_bounds__(256, 1)
nv_prep(const float* __restrict__ cent) {
    const int w = threadIdx.x >> 5, l = threadIdx.x & 31;
    #pragma unroll
    for (int k = w; k < KK; k += 8) {
        float4 v = ((const float4*)cent)[k * 32 + l];
        half2 h01 = __floats2half2_rn(v.x, v.y);
        half2 h23 = __floats2half2_rn(v.z, v.w);
        uint2 u;
        u.x = *(uint32_t*)&h01;
        u.y = *(uint32_t*)&h23;
        *(uint2*)&g_Ch[k * DD + 4 * l] = u;
        float2 f01 = __half22float2(h01), f23 = __half22float2(h23);
        float s = f01.x * f01.x + f01.y * f01.y + f23.x * f23.x + f23.y * f23.y;
        #pragma unroll
        for (int o = 16; o; o >>= 1) s += __shfl_xor_sync(~0u, s, o);
        if (l == 0) g_cn2[k] = s;
    }
}

// ---------------------------------------------------------------------------
// Fused kernel: grid = (64 tiles, 8 b) = 512 CTAs, 256 threads (8 warps),
// 4 CTAs/SM worst case (all co-resident -> spin barrier deadlock-free).
// Warps 0-3: GEMM1 + softmax (n only 32 wide). All 8 warps: loads, GEMM2
// (d split 8 ways), partial stores, phase-2 reduction (8 tiles/warp).
// ---------------------------------------------------------------------------
__global__ void __launch_bounds__(256, 4)
nv_main(const float* __restrict__ x, const float* __restrict__ cent,
        float* __restrict__ out) {
    extern __shared__ char smc[];
    half*  xs  = (half*)(smc + O_XS);
    half*  At  = (half*)(smc + O_AT);
    float* cn2 = (float*)(smc + O_CN2);
    float* ssm = (float*)(smc + O_SSM);
    float* red = (float*)(smc + O_RED);
    const uint32_t sb = (uint32_t)__cvta_generic_to_shared(smc);

    const int tid = threadIdx.x, w = tid >> 5, l = tid & 31;
    const int g = l >> 2, t = l & 3;           // mma groupID / thread-in-group
    const int b = blockIdx.y, tile = blockIdx.x;

    if (tid < 64) {
        ssm[tid] = 0.f;
        cn2[tid] = g_cn2[tid];
    }

    // ---- phase A: copy fp16 C -> smem; load x rows (4/warp), normalize ----
    {
        const float4* x4 = (const float4*)(x + ((size_t)b * NN + (size_t)tile * TT) * DD);
        float4 xv[4];
        #pragma unroll
        for (int i = 0; i < 4; i++) xv[i] = x4[(w * 4 + i) * 32 + l];

        half* Cs = (half*)(smc + O_CS);
        const uint4* Cg = (const uint4*)g_Ch;
        #pragma unroll
        for (int i = tid; i < KK * DD / 8; i += 256) {   // 1024 uint4s
            uint4 v = Cg[i];
            int k = i >> 4, off = (i & 15) * 8;
            *(uint4*)&Cs[k * STRC + off] = v;
        }

        #pragma unroll
        for (int i = 0; i < 4; i++) {
            float4 v = xv[i];
            float ss = v.x * v.x + v.y * v.y + v.z * v.z + v.w * v.w;
            #pragma unroll
            for (int o = 16; o; o >>= 1) ss += __shfl_xor_sync(~0u, ss, o);
            float ri = frsqrt(fmaxf(ss, 1e-24f));
            int r = w * 4 + i;
            *(half2*)&xs[r * STRC + 4 * l]     = __floats2half2_rn(v.x * ri, v.y * ri);
            *(half2*)&xs[r * STRC + 4 * l + 2] = __floats2half2_rn(v.z * ri, v.w * ri);
        }
    }
    __syncthreads();

    // ---- GEMM1 + softmax + At: warps 0-3 only (n is 32 wide) ----
    if (w < 4) {
        const int nb = w * 8;
        const uint32_t* Xw = (const uint32_t*)xs;
        const uint32_t aAddr1 = sb + O_CS + (uint32_t)((l & 15) * 272 + (l >> 4) * 16);
        float acc[4][4];
        #pragma unroll
        for (int mt = 0; mt < 4; mt++)
            #pragma unroll
            for (int q = 0; q < 4; q++) acc[mt][q] = 0.f;

        #pragma unroll
        for (int s = 0; s < 8; s++) {
            uint32_t a[4][4], bf[2];
            #pragma unroll
            for (int mt = 0; mt < 4; mt++)
                LDSM4(a[mt], aAddr1 + mt * 4352 + s * 32);
            int bb2 = (nb + g) * 68 + 8 * s + t;
            bf[0] = Xw[bb2];
            bf[1] = Xw[bb2 + 4];
            #pragma unroll
            for (int mt = 0; mt < 4; mt++) mma16(acc[mt], a[mt], bf);
        }

        // softmax per n-column over k=64 (warp-local; args tiny -> no max shift)
        float s0 = 0.f, s1 = 0.f;
        #pragma unroll
        for (int mt = 0; mt < 4; mt++) {
            float cA = cn2[mt * 16 + g], cB = cn2[mt * 16 + g + 8];
            acc[mt][0] = fexp(fmaf(-2.f, acc[mt][0], cA));
            acc[mt][1] = fexp(fmaf(-2.f, acc[mt][1], cA));
            acc[mt][2] = fexp(fmaf(-2.f, acc[mt][2], cB));
            acc[mt][3] = fexp(fmaf(-2.f, acc[mt][3], cB));
            s0 += acc[mt][0] + acc[mt][2];
            s1 += acc[mt][1] + acc[mt][3];
        }
        #pragma unroll
        for (int o = 4; o <= 16; o <<= 1) {
            s0 += __shfl_xor_sync(~0u, s0, o);
            s1 += __shfl_xor_sync(~0u, s1, o);
        }
        s0 = frcp(s0);
        s1 = frcp(s1);

        #pragma unroll
        for (int mt = 0; mt < 4; mt++) {
            float a0 = acc[mt][0] * s0, a1 = acc[mt][1] * s1;
            float a2 = acc[mt][2] * s0, a3 = acc[mt][3] * s1;
            float rs0 = a0 + a1, rs1 = a2 + a3;
            int rr = mt * 16 + g;
            *(half2*)&At[rr * STRA + nb + 2 * t]       = __floats2half2_rn(a0, a1);
            *(half2*)&At[(rr + 8) * STRA + nb + 2 * t] = __floats2half2_rn(a2, a3);
            rs0 += __shfl_xor_sync(~0u, rs0, 1);
            rs0 += __shfl_xor_sync(~0u, rs0, 2);
            rs1 += __shfl_xor_sync(~0u, rs1, 1);
            rs1 += __shfl_xor_sync(~0u, rs1, 2);
            if (t == 0) {
                atomicAdd(&ssm[rr], rs0);
                atomicAdd(&ssm[rr + 8], rs1);
            }
        }
    }
    __syncthreads();

    // ---- GEMM2: P[k][d] = At[k][n] * Xn[n][d] ; warp w: d in [16w,16w+16) ----
    {
        const unsigned short* Xu = (const unsigned short*)xs;
        const uint32_t aAddr2 = sb + O_AT + (uint32_t)((l & 15) * 80 + (l >> 4) * 16);
        const int db = 16 * w;
        float pc[4][2][4];
        #pragma unroll
        for (int mt = 0; mt < 4; mt++)
            #pragma unroll
            for (int nt = 0; nt < 2; nt++)
                #pragma unroll
                for (int q = 0; q < 4; q++) pc[mt][nt][q] = 0.f;

        #pragma unroll
        for (int s = 0; s < 2; s++) {
            uint32_t a[4][4];
            #pragma unroll
            for (int mt = 0; mt < 4; mt++)
                LDSM4(a[mt], aAddr2 + mt * 1280 + s * 32);
            #pragma unroll
            for (int nt = 0; nt < 2; nt++) {
                int dcol = db + 8 * nt + g;
                int rh = (16 * s + 2 * t) * STRC + dcol;
                uint32_t lo0 = Xu[rh],            hi0 = Xu[rh + STRC];
                uint32_t lo1 = Xu[rh + 8 * STRC], hi1 = Xu[rh + 9 * STRC];
                uint32_t bfr[2] = { lo0 | (hi0 << 16), lo1 | (hi1 << 16) };
                #pragma unroll
                for (int mt = 0; mt < 4; mt++) mma16(pc[mt][nt], a[mt], bfr);
            }
        }

        // store per-tile partials
        float* Pb = g_Pp + (size_t)(b * TILES + tile) * KK * DD;
        #pragma unroll
        for (int mt = 0; mt < 4; mt++)
            #pragma unroll
            for (int nt = 0; nt < 2; nt++) {
                int rr = mt * 16 + g, dd2 = db + 8 * nt + 2 * t;
                *(float2*)&Pb[rr * DD + dd2]       = make_float2(pc[mt][nt][0], pc[mt][nt][1]);
                *(float2*)&Pb[(rr + 8) * DD + dd2] = make_float2(pc[mt][nt][2], pc[mt][nt][3]);
            }
    }
    if (tid < 64) g_sp[(b * TILES + tile) * KK + tid] = ssm[tid];

    // ================= cross-CTA barrier (per b, 64 arrivals) =================
    __threadfence();
    __syncthreads();
    if (tid == 0) {
        atomicAdd(&g_arr[b], 1u);
        volatile unsigned int* va = &g_arr[b];
        while (*va < TILES) __nanosleep(64);
        __threadfence();
        unsigned int my = atomicAdd(&g_dep[b], 1u);
        if (my == TILES - 1) { g_arr[b] = 0u; g_dep[b] = 0u; }
    }
    __syncthreads();

    // ================= phase 2: CTA (b,tile) finalizes k = tile =================
    // Warp w reduces tiles [8w,8w+8) with float4 loads; 8x128 stage in smem;
    // threads 0-127 combine + epilogue.
    {
        const int k = tile;
        float* ps = (float*)smc;   // reuse Cs region (dead): 8*128 floats = 4KB
        const float4* P4 = (const float4*)g_Pp;
        float4 a = make_float4(0.f, 0.f, 0.f, 0.f);
        #pragma unroll
        for (int tt = w * 8; tt < w * 8 + 8; tt++) {
            float4 v = __ldcg(&P4[((size_t)(b * TILES + tt) * KK + k) * 32 + l]);
            a.x += v.x; a.y += v.y; a.z += v.z; a.w += v.w;
        }
        ((float4*)(ps + w * 128))[l] = a;

        float sv = 0.f;
        if (tid < 64) sv = __ldcg(&g_sp[(b * TILES + tid) * KK + k]);
        #pragma unroll
        for (int o = 16; o; o >>= 1) sv += __shfl_xor_sync(~0u, sv, o);
        if (l == 0 && w < 2) red[w] = sv;
        __syncthreads();

        float v = 0.f;
        if (tid < 128) {
            const int d = tid;
            float v0 = (ps[d] + ps[128 + d]) + (ps[256 + d] + ps[384 + d]);
            float v1 = (ps[512 + d] + ps[640 + d]) + (ps[768 + d] + ps[896 + d]);
            v = v0 + v1;
            float sk = red[0] + red[1];
            v = fmaf(-sk, cent[k * DD + d], v);
            float ssq = v * v;
            #pragma unroll
            for (int o = 16; o; o >>= 1) ssq += __shfl_xor_sync(~0u, ssq, o);
            if (l == 0) red[8 + w] = ssq;
        }
        __syncthreads();
        if (tid < 128) {
            float tot = (red[8] + red[9]) + (red[10] + red[11]);
            float sc = 0.125f * frsqrt(fmaxf(tot, 1e-24f));   // exact global norm = 8
            out[((size_t)b * KK + k) * DD + tid] = v * sc;
        }
    }
}

// ---------------------------------------------------------------------------
extern "C" void kernel_launch(void* const* d_in, const int* in_sizes, int n_in,
                              void* d_out, int out_size) {
    (void)in_sizes; (void)n_in; (void)out_size;
    const float* x    = (const float*)d_in[0];
    const float* cent = (const float*)d_in[1];
    float* out        = (float*)d_out;

    cudaFuncSetAttribute(nv_main, cudaFuncAttributeMaxDynamicSharedMemorySize, SMEMB);
    nv_prep<<<1, 256>>>(cent);
    nv_main<<<dim3(TILES, BB), 256, SMEMB>>>(x, cent, out);
}

// round 14
// speedup vs baseline: 1.0928x; 1.0928x over previous
#include <cuda_runtime.h>
#include <cuda_fp16.h>
#include <cstdint>
#include <math.h>

#define BB 8
#define NN 2048
#define DD 128
#define KK 64
#define TT2 64      // rows per CTA (2 sub-tiles of 32)
#define TILES2 32   // NN / TT2

// per-tile partials (fully rewritten every launch -> no zero kernel)
__device__ float g_Pp[BB * TILES2 * KK * DD];   // 8 MB (L2-resident)
__device__ float g_sp[BB * TILES2 * KK];
__device__ unsigned int g_arr[BB];
__device__ unsigned int g_dep[BB];
__device__ half  g_Ch[KK * DD];                 // fp16 centroids (prep kernel)
__device__ float g_cn2[KK];                     // ||c_k||^2 from rounded halves

// half strides: Cs/xs rows = 136 halves; At rows = 40 halves
#define STRC 136
#define STRA 40

// smem byte offsets
#define O_CS   0                        // 64*136*2 = 17408
#define O_XS   17408                    // 64*136*2 = 17408
#define O_AT   34816                    // 64*40*2  = 5120
#define O_CN2  39936                    // 64 floats
#define O_SSM  40192                    // 64 floats
#define O_RED  40448                    // 16 floats
#define SMEMB  40512

// ---- FFMA-only transcendentals (avoid the 0.5 op/cyc/SM MUFU pipe) ----
__device__ __forceinline__ float fexp(float x) {      // e^x, |x| small here
    float y = x * 1.4426950408889634f;
    float t = y + 12582912.f;                          // round-to-nearest int
    int j = __float_as_int(t) << 23;
    float f = y - (t - 12582912.f);                    // frac in [-0.5, 0.5]
    float p = 1.3333558e-3f;
    p = fmaf(p, f, 9.6181291e-3f);
    p = fmaf(p, f, 5.5504109e-2f);
    p = fmaf(p, f, 2.4022648e-1f);
    p = fmaf(p, f, 6.9314718e-1f);
    p = fmaf(p, f, 1.0f);
    return __int_as_float(__float_as_int(p) + j);
}
__device__ __forceinline__ float frsqrt(float s) {    // 1/sqrt(s), s > 0
    float h = __int_as_float(0x5f375a86 - (__float_as_int(s) >> 1));
    h = h * fmaf(-0.5f * s, h * h, 1.5f);
    h = h * fmaf(-0.5f * s, h * h, 1.5f);
    return h;
}
__device__ __forceinline__ float frcp(float s) {      // 1/s, s > 0
    float r = __int_as_float(0x7ef311c3 - __float_as_int(s));
    r = r * fmaf(-s, r, 2.0f);
    r = r * fmaf(-s, r, 2.0f);
    return r;
}

__device__ __forceinline__ void mma16(float* d, const uint32_t* a, const uint32_t* b) {
    asm volatile(
        "mma.sync.aligned.m16n8k16.row.col.f32.f16.f16.f32 "
        "{%0,%1,%2,%3}, {%4,%5,%6,%7}, {%8,%9}, {%0,%1,%2,%3};"
        : "+f"(d[0]), "+f"(d[1]), "+f"(d[2]), "+f"(d[3])
        : "r"(a[0]), "r"(a[1]), "r"(a[2]), "r"(a[3]), "r"(b[0]), "r"(b[1]));
}
#define LDSM4(r, addr) \
    asm volatile("ldmatrix.sync.aligned.m8n8.x4.shared.b16 {%0,%1,%2,%3}, [%4];" \
        : "=r"((r)[0]), "=r"((r)[1]), "=r"((r)[2]), "=r"((r)[3]) : "r"(addr))

// ---------------------------------------------------------------------------
// prep: convert C to fp16 + cn2 from rounded halves. 1 block, 256 threads.
// ---------------------------------------------------------------------------
__global__ void __launch_bounds__(256, 1)
nv_prep(const float* __restrict__ cent) {
    const int w = threadIdx.x >> 5, l = threadIdx.x & 31;
    #pragma unroll
    for (int k = w; k < KK; k += 8) {
        float4 v = ((const float4*)cent)[k * 32 + l];
        half2 h01 = __floats2half2_rn(v.x, v.y);
        half2 h23 = __floats2half2_rn(v.z, v.w);
        uint2 u;
        u.x = *(uint32_t*)&h01;
        u.y = *(uint32_t*)&h23;
        *(uint2*)&g_Ch[k * DD + 4 * l] = u;
        float2 f01 = __half22float2(h01), f23 = __half22float2(h23);
        float s = f01.x * f01.x + f01.y * f01.y + f23.x * f23.x + f23.y * f23.y;
        #pragma unroll
        for (int o = 16; o; o >>= 1) s += __shfl_xor_sync(~0u, s, o);
        if (l == 0) g_cn2[k] = s;
    }
}

// ---------------------------------------------------------------------------
// Fused kernel: grid = (32 tilepairs, 8 b) = 256 CTAs, 256 threads, 2 CTAs/SM
// worst case (256 <= 296 slots -> all co-resident, spin barrier safe).
// Each CTA: 64 rows in 2 sub-tiles of 32; C loaded once; GEMM2 accumulates
// in registers across sub-tiles; ONE partial store. Phase 2: 2 k's per CTA.
// ---------------------------------------------------------------------------
__global__ void __launch_bounds__(256, 2)
nv_main(const float* __restrict__ x, const float* __restrict__ cent,
        float* __restrict__ out) {
    extern __shared__ char smc[];
    half*  xs  = (half*)(smc + O_XS);
    half*  At  = (half*)(smc + O_AT);
    float* cn2 = (float*)(smc + O_CN2);
    float* ssm = (float*)(smc + O_SSM);
    float* red = (float*)(smc + O_RED);
    const uint32_t sb = (uint32_t)__cvta_generic_to_shared(smc);

    const int tid = threadIdx.x, w = tid >> 5, l = tid & 31;
    const int g = l >> 2, t = l & 3;           // mma groupID / thread-in-group
    const int b = blockIdx.y, tile = blockIdx.x;

    if (tid < 64) {
        ssm[tid] = 0.f;
        cn2[tid] = g_cn2[tid];
    }

    // ---- phase A: copy fp16 C -> smem once; load 64 x rows (8/warp), norm ----
    {
        const float4* x4 = (const float4*)(x + ((size_t)b * NN + (size_t)tile * TT2) * DD);
        float4 xv[8];
        #pragma unroll
        for (int i = 0; i < 8; i++) xv[i] = x4[(w * 8 + i) * 32 + l];

        half* Cs = (half*)(smc + O_CS);
        const uint4* Cg = (const uint4*)g_Ch;
        #pragma unroll
        for (int i = tid; i < KK * DD / 8; i += 256) {
            uint4 v = Cg[i];
            int k = i >> 4, off = (i & 15) * 8;
            *(uint4*)&Cs[k * STRC + off] = v;
        }

        #pragma unroll
        for (int i = 0; i < 8; i++) {
            float4 v = xv[i];
            float ss = v.x * v.x + v.y * v.y + v.z * v.z + v.w * v.w;
            #pragma unroll
            for (int o = 16; o; o >>= 1) ss += __shfl_xor_sync(~0u, ss, o);
            float ri = frsqrt(fmaxf(ss, 1e-24f));
            int r = w * 8 + i;
            *(half2*)&xs[r * STRC + 4 * l]     = __floats2half2_rn(v.x * ri, v.y * ri);
            *(half2*)&xs[r * STRC + 4 * l + 2] = __floats2half2_rn(v.z * ri, v.w * ri);
        }
    }
    __syncthreads();

    // ---- persistent GEMM2 accumulators (d split 8 ways: warp w -> [16w,16w+16)) ----
    float pc[4][2][4];
    #pragma unroll
    for (int mt = 0; mt < 4; mt++)
        #pragma unroll
        for (int nt = 0; nt < 2; nt++)
            #pragma unroll
            for (int q = 0; q < 4; q++) pc[mt][nt][q] = 0.f;

    const uint32_t aAddr1 = sb + O_CS + (uint32_t)((l & 15) * 272 + (l >> 4) * 16);
    const uint32_t aAddr2 = sb + O_AT + (uint32_t)((l & 15) * 80 + (l >> 4) * 16);

    #pragma unroll
    for (int s2 = 0; s2 < 2; s2++) {
        // ---- GEMM1 + softmax + At: warps 0-3 (rows s2*32 .. s2*32+32) ----
        if (w < 4) {
            const int nb = w * 8;
            const uint32_t* Xw = (const uint32_t*)xs;
            float acc[4][4];
            #pragma unroll
            for (int mt = 0; mt < 4; mt++)
                #pragma unroll
                for (int q = 0; q < 4; q++) acc[mt][q] = 0.f;

            #pragma unroll
            for (int s = 0; s < 8; s++) {
                uint32_t a[4][4], bf[2];
                #pragma unroll
                for (int mt = 0; mt < 4; mt++)
                    LDSM4(a[mt], aAddr1 + mt * 4352 + s * 32);
                int bb2 = (s2 * 32 + nb + g) * 68 + 8 * s + t;
                bf[0] = Xw[bb2];
                bf[1] = Xw[bb2 + 4];
                #pragma unroll
                for (int mt = 0; mt < 4; mt++) mma16(acc[mt], a[mt], bf);
            }

            // softmax per n-column over k=64 (args tiny -> no max shift)
            float s0 = 0.f, s1 = 0.f;
            #pragma unroll
            for (int mt = 0; mt < 4; mt++) {
                float cA = cn2[mt * 16 + g], cB = cn2[mt * 16 + g + 8];
                acc[mt][0] = fexp(fmaf(-2.f, acc[mt][0], cA));
                acc[mt][1] = fexp(fmaf(-2.f, acc[mt][1], cA));
                acc[mt][2] = fexp(fmaf(-2.f, acc[mt][2], cB));
                acc[mt][3] = fexp(fmaf(-2.f, acc[mt][3], cB));
                s0 += acc[mt][0] + acc[mt][2];
                s1 += acc[mt][1] + acc[mt][3];
            }
            #pragma unroll
            for (int o = 4; o <= 16; o <<= 1) {
                s0 += __shfl_xor_sync(~0u, s0, o);
                s1 += __shfl_xor_sync(~0u, s1, o);
            }
            s0 = frcp(s0);
            s1 = frcp(s1);

            #pragma unroll
            for (int mt = 0; mt < 4; mt++) {
                float a0 = acc[mt][0] * s0, a1 = acc[mt][1] * s1;
                float a2 = acc[mt][2] * s0, a3 = acc[mt][3] * s1;
                float rs0 = a0 + a1, rs1 = a2 + a3;
                int rr = mt * 16 + g;
                *(half2*)&At[rr * STRA + nb + 2 * t]       = __floats2half2_rn(a0, a1);
                *(half2*)&At[(rr + 8) * STRA + nb + 2 * t] = __floats2half2_rn(a2, a3);
                rs0 += __shfl_xor_sync(~0u, rs0, 1);
                rs0 += __shfl_xor_sync(~0u, rs0, 2);
                rs1 += __shfl_xor_sync(~0u, rs1, 1);
                rs1 += __shfl_xor_sync(~0u, rs1, 2);
                if (t == 0) {
                    atomicAdd(&ssm[rr], rs0);
                    atomicAdd(&ssm[rr + 8], rs1);
                }
            }
        }
        __syncthreads();

        // ---- GEMM2 accumulate: all 8 warps; B rows offset by s2*32 ----
        {
            const unsigned short* Xu = (const unsigned short*)xs;
            const int db = 16 * w;
            #pragma unroll
            for (int s = 0; s < 2; s++) {
                uint32_t a[4][4];
                #pragma unroll
                for (int mt = 0; mt < 4; mt++)
                    LDSM4(a[mt], aAddr2 + mt * 1280 + s * 32);
                #pragma unroll
                for (int nt = 0; nt < 2; nt++) {
                    int dcol = db + 8 * nt + g;
                    int rh = (s2 * 32 + 16 * s + 2 * t) * STRC + dcol;
                    uint32_t lo0 = Xu[rh],            hi0 = Xu[rh + STRC];
                    uint32_t lo1 = Xu[rh + 8 * STRC], hi1 = Xu[rh + 9 * STRC];
                    uint32_t bfr[2] = { lo0 | (hi0 << 16), lo1 | (hi1 << 16) };
                    #pragma unroll
                    for (int mt = 0; mt < 4; mt++) mma16(pc[mt][nt], a[mt], bfr);
                }
            }
        }
        __syncthreads();   // protect At before next sub-tile overwrites it
    }

    // ---- ONE partial store for the 64-row pair ----
    {
        float* Pb = g_Pp + (size_t)(b * TILES2 + tile) * KK * DD;
        const int db = 16 * w;
        #pragma unroll
        for (int mt = 0; mt < 4; mt++)
            #pragma unroll
            for (int nt = 0; nt < 2; nt++) {
                int rr = mt * 16 + g, dd2 = db + 8 * nt + 2 * t;
                *(float2*)&Pb[rr * DD + dd2]       = make_float2(pc[mt][nt][0], pc[mt][nt][1]);
                *(float2*)&Pb[(rr + 8) * DD + dd2] = make_float2(pc[mt][nt][2], pc[mt][nt][3]);
            }
        if (tid < 64) g_sp[(b * TILES2 + tile) * KK + tid] = ssm[tid];
    }

    // ================= cross-CTA barrier (per b, 32 arrivals) =================
    __threadfence();
    __syncthreads();
    if (tid == 0) {
        atomicAdd(&g_arr[b], 1u);
        volatile unsigned int* va = &g_arr[b];
        while (*va < TILES2) __nanosleep(64);
        __threadfence();
        unsigned int my = atomicAdd(&g_dep[b], 1u);
        if (my == TILES2 - 1) { g_arr[b] = 0u; g_dep[b] = 0u; }
    }
    __syncthreads();

    // ================= phase 2: CTA (b,tile) finalizes k = 2*tile + {0,1} ====
    // Warps 0-3 -> k0 (8 tiles each), warps 4-7 -> k0+1. float4 loads, smem
    // stage, 256-thread combine + epilogue.
    {
        const int k0 = tile * 2;
        const int kh = w >> 2, wsub = w & 3;
        const int k = k0 + kh;
        float* ps = (float*)smc;   // reuse Cs region (dead): 2*512 floats = 4KB
        const float4* P4 = (const float4*)g_Pp;
        float4 a = make_float4(0.f, 0.f, 0.f, 0.f);
        #pragma unroll
        for (int tt = wsub * 8; tt < wsub * 8 + 8; tt++) {
            float4 v = __ldcg(&P4[((size_t)(b * TILES2 + tt) * KK + k) * 32 + l]);
            a.x += v.x; a.y += v.y; a.z += v.z; a.w += v.w;
        }
        ((float4*)(ps + kh * 512 + wsub * 128))[l] = a;

        // s[k]: warps 0 (k0) and 4 (k0+1); lane = tile index
        if (wsub == 0) {
            float sv = __ldcg(&g_sp[(b * TILES2 + l) * KK + k]);
            #pragma unroll
            for (int o = 16; o; o >>= 1) sv += __shfl_xor_sync(~0u, sv, o);
            if (l == 0) red[kh] = sv;
        }
        __syncthreads();

        const int kk = tid >> 7, d = tid & 127;   // warp-uniform kk (= w>>2)
        float v = (ps[kk * 512 + d] + ps[kk * 512 + 128 + d]) +
                  (ps[kk * 512 + 256 + d] + ps[kk * 512 + 384 + d]);
        float sk = red[kk];
        v = fmaf(-sk, cent[(k0 + kk) * DD + d], v);
        float ssq = v * v;
        #pragma unroll
        for (int o = 16; o; o >>= 1) ssq += __shfl_xor_sync(~0u, ssq, o);
        if (l == 0) red[8 + w] = ssq;
        __syncthreads();
        float tot = (red[8 + kk * 4] + red[9 + kk * 4]) +
                    (red[10 + kk * 4] + red[11 + kk * 4]);
        float sc = 0.125f * frsqrt(fmaxf(tot, 1e-24f));   // exact global norm = 8
        out[((size_t)b * KK + k0 + kk) * DD + d] = v * sc;
    }
}

// ---------------------------------------------------------------------------
extern "C" void kernel_launch(void* const* d_in, const int* in_sizes, int n_in,
                              void* d_out, int out_size) {
    (void)in_sizes; (void)n_in; (void)out_size;
    const float* x    = (const float*)d_in[0];
    const float* cent = (const float*)d_in[1];
    float* out        = (float*)d_out;

    cudaFuncSetAttribute(nv_main, cudaFuncAttributeMaxDynamicSharedMemorySize, SMEMB);
    nv_prep<<<1, 256>>>(cent);
    nv_main<<<dim3(TILES2, BB), 256, SMEMB>>>(x, cent, out);
}

// round 15
// speedup vs baseline: 1.2435x; 1.1379x over previous
#include <cuda_runtime.h>
#include <cuda_fp16.h>
#include <cstdint>
#include <math.h>

#define BB 8
#define NN 2048
#define DD 128
#define KK 64
#define ROWS 128    // rows per CTA
#define TILES 16    // NN / ROWS

// per-tile partials (fully rewritten every launch -> no zero kernel)
__device__ float g_Pp[BB * TILES * KK * DD];   // 4 MB (L2-resident)
__device__ float g_sp[BB * TILES * KK];
__device__ unsigned int g_arr[BB];
__device__ unsigned int g_dep[BB];

// half strides: Cs/xs rows = 136 halves; At rows = 72 halves (n=64 + pad)
#define STRC 136
#define STRA 72

// smem byte offsets
#define O_CS   0                        // 64*136*2  = 17408
#define O_XS   17408                    // 128*136*2 = 34816
#define O_AT   52224                    // 64*72*2   = 9216
#define O_CN2  61440                    // 64 floats
#define O_SSM  61696                    // 64 floats
#define O_RED  61952                    // 32 floats
#define SMEMB  62080

// ---- FFMA-only transcendentals (avoid the 0.5 op/cyc/SM MUFU pipe) ----
__device__ __forceinline__ float fexp(float x) {      // e^x, |x| small here
    float y = x * 1.4426950408889634f;
    float t = y + 12582912.f;
    int j = __float_as_int(t) << 23;
    float f = y - (t - 12582912.f);
    float p = 1.3333558e-3f;
    p = fmaf(p, f, 9.6181291e-3f);
    p = fmaf(p, f, 5.5504109e-2f);
    p = fmaf(p, f, 2.4022648e-1f);
    p = fmaf(p, f, 6.9314718e-1f);
    p = fmaf(p, f, 1.0f);
    return __int_as_float(__float_as_int(p) + j);
}
__device__ __forceinline__ float frsqrt(float s) {
    float h = __int_as_float(0x5f375a86 - (__float_as_int(s) >> 1));
    h = h * fmaf(-0.5f * s, h * h, 1.5f);
    h = h * fmaf(-0.5f * s, h * h, 1.5f);
    return h;
}
__device__ __forceinline__ float frcp(float s) {
    float r = __int_as_float(0x7ef311c3 - __float_as_int(s));
    r = r * fmaf(-s, r, 2.0f);
    r = r * fmaf(-s, r, 2.0f);
    return r;
}

__device__ __forceinline__ void mma16(float* d, const uint32_t* a, const uint32_t* b) {
    asm volatile(
        "mma.sync.aligned.m16n8k16.row.col.f32.f16.f16.f32 "
        "{%0,%1,%2,%3}, {%4,%5,%6,%7}, {%8,%9}, {%0,%1,%2,%3};"
        : "+f"(d[0]), "+f"(d[1]), "+f"(d[2]), "+f"(d[3])
        : "r"(a[0]), "r"(a[1]), "r"(a[2]), "r"(a[3]), "r"(b[0]), "r"(b[1]));
}
#define LDSM4(r, addr) \
    asm volatile("ldmatrix.sync.aligned.m8n8.x4.shared.b16 {%0,%1,%2,%3}, [%4];" \
        : "=r"((r)[0]), "=r"((r)[1]), "=r"((r)[2]), "=r"((r)[3]) : "r"(addr))

// ---------------------------------------------------------------------------
// Fused kernel: grid = (16 tiles, 8 b) = 128 CTAs, 256 threads, 1 CTA/SM
// (128 <= 148 -> all co-resident, perfectly balanced, spin barrier safe).
// Each CTA: 128 rows in 2 iterations of 64 (two 32-row halves in parallel:
// warps 0-3 sub-tile A, warps 4-7 sub-tile B for GEMM1/softmax; all 8 warps
// for GEMM2 with register accumulation). ONE partial store.
// Phase 2: 4 k-columns per CTA.
// ---------------------------------------------------------------------------
__global__ void __launch_bounds__(256)
nv_main(const float* __restrict__ x, const float* __restrict__ cent,
        float* __restrict__ out) {
    extern __shared__ char smc[];
    half*  xs  = (half*)(smc + O_XS);
    half*  At  = (half*)(smc + O_AT);
    float* cn2 = (float*)(smc + O_CN2);
    float* ssm = (float*)(smc + O_SSM);
    float* red = (float*)(smc + O_RED);
    const uint32_t sb = (uint32_t)__cvta_generic_to_shared(smc);

    const int tid = threadIdx.x, w = tid >> 5, l = tid & 31;
    const int g = l >> 2, t = l & 3;           // mma groupID / thread-in-group
    const int b = blockIdx.y, tile = blockIdx.x;
    const int h = w >> 2, ws = w & 3;          // sub-tile half / warp-in-half
    const int nb = ws * 8;

    if (tid < 64) ssm[tid] = 0.f;

    // ---- phase A: convert C -> fp16 smem (once per SM); load+norm 128 x rows ----
    {
        half* Cs = (half*)(smc + O_CS);
        const float4* c4 = (const float4*)cent;
        const float4* x4 = (const float4*)(x + ((size_t)b * NN + (size_t)tile * ROWS) * DD);

        float4 xv[8];
        #pragma unroll
        for (int i = 0; i < 8; i++) xv[i] = x4[(w * 16 + i) * 32 + l];

        #pragma unroll
        for (int i = tid; i < KK * DD / 4; i += 256) {
            float4 v = c4[i];
            int k = i >> 5, d4 = (i & 31) * 4;
            *(half2*)&Cs[k * STRC + d4]     = __floats2half2_rn(v.x, v.y);
            *(half2*)&Cs[k * STRC + d4 + 2] = __floats2half2_rn(v.z, v.w);
        }

        #pragma unroll
        for (int i = 0; i < 8; i++) {
            float4 v = xv[i];
            float ss = v.x * v.x + v.y * v.y + v.z * v.z + v.w * v.w;
            #pragma unroll
            for (int o = 16; o; o >>= 1) ss += __shfl_xor_sync(~0u, ss, o);
            float ri = frsqrt(fmaxf(ss, 1e-24f));
            int r = w * 16 + i;
            *(half2*)&xs[r * STRC + 4 * l]     = __floats2half2_rn(v.x * ri, v.y * ri);
            *(half2*)&xs[r * STRC + 4 * l + 2] = __floats2half2_rn(v.z * ri, v.w * ri);
        }
        #pragma unroll
        for (int i = 0; i < 8; i++) xv[i] = x4[(w * 16 + 8 + i) * 32 + l];
        #pragma unroll
        for (int i = 0; i < 8; i++) {
            float4 v = xv[i];
            float ss = v.x * v.x + v.y * v.y + v.z * v.z + v.w * v.w;
            #pragma unroll
            for (int o = 16; o; o >>= 1) ss += __shfl_xor_sync(~0u, ss, o);
            float ri = frsqrt(fmaxf(ss, 1e-24f));
            int r = w * 16 + 8 + i;
            *(half2*)&xs[r * STRC + 4 * l]     = __floats2half2_rn(v.x * ri, v.y * ri);
            *(half2*)&xs[r * STRC + 4 * l + 2] = __floats2half2_rn(v.z * ri, v.w * ri);
        }
    }
    __syncthreads();

    // ---- cn2[k] = ||c_k||^2 from rounded halves ----
    if (tid < 128) {
        const half* Cs = (const half*)(smc + O_CS);
        int kc = tid >> 1, q = tid & 1;
        float s = 0.f;
        #pragma unroll
        for (int j = 0; j < 32; j++) {
            float2 f = __half22float2(*(const half2*)&Cs[kc * STRC + q * 64 + 2 * j]);
            s += f.x * f.x + f.y * f.y;
        }
        s += __shfl_xor_sync(~0u, s, 1);
        if (q == 0) cn2[kc] = s;
    }
    __syncthreads();

    // ---- persistent GEMM2 accumulators: warp w -> d in [16w, 16w+16) ----
    float pc[4][2][4];
    #pragma unroll
    for (int mt = 0; mt < 4; mt++)
        #pragma unroll
        for (int nt = 0; nt < 2; nt++)
            #pragma unroll
            for (int q = 0; q < 4; q++) pc[mt][nt][q] = 0.f;

    const uint32_t aAddr1 = sb + O_CS + (uint32_t)((l & 15) * 272 + (l >> 4) * 16);
    const uint32_t aAddr2 = sb + O_AT + (uint32_t)((l & 15) * 144 + (l >> 4) * 16);

    #pragma unroll
    for (int iter = 0; iter < 2; iter++) {
        // ---- GEMM1 + softmax: ALL 8 warps (h picks 32-row half of 64-row block) ----
        {
            const int rowbase = iter * 64 + h * 32;
            const uint32_t* Xw = (const uint32_t*)xs;
            float acc[4][4];
            #pragma unroll
            for (int mt = 0; mt < 4; mt++)
                #pragma unroll
                for (int q = 0; q < 4; q++) acc[mt][q] = 0.f;

            #pragma unroll
            for (int s = 0; s < 8; s++) {
                uint32_t a[4][4], bf[2];
                #pragma unroll
                for (int mt = 0; mt < 4; mt++)
                    LDSM4(a[mt], aAddr1 + mt * 4352 + s * 32);
                int bb2 = (rowbase + nb + g) * 68 + 8 * s + t;
                bf[0] = Xw[bb2];
                bf[1] = Xw[bb2 + 4];
                #pragma unroll
                for (int mt = 0; mt < 4; mt++) mma16(acc[mt], a[mt], bf);
            }

            // softmax per n-column over k=64 (args tiny -> no max shift)
            float s0 = 0.f, s1 = 0.f;
            #pragma unroll
            for (int mt = 0; mt < 4; mt++) {
                float cA = cn2[mt * 16 + g], cB = cn2[mt * 16 + g + 8];
                acc[mt][0] = fexp(fmaf(-2.f, acc[mt][0], cA));
                acc[mt][1] = fexp(fmaf(-2.f, acc[mt][1], cA));
                acc[mt][2] = fexp(fmaf(-2.f, acc[mt][2], cB));
                acc[mt][3] = fexp(fmaf(-2.f, acc[mt][3], cB));
                s0 += acc[mt][0] + acc[mt][2];
                s1 += acc[mt][1] + acc[mt][3];
            }
            #pragma unroll
            for (int o = 4; o <= 16; o <<= 1) {
                s0 += __shfl_xor_sync(~0u, s0, o);
                s1 += __shfl_xor_sync(~0u, s1, o);
            }
            s0 = frcp(s0);
            s1 = frcp(s1);

            // assign -> At[k][n] (col base = h*32 + nb) + row sums -> ssm
            #pragma unroll
            for (int mt = 0; mt < 4; mt++) {
                float a0 = acc[mt][0] * s0, a1 = acc[mt][1] * s1;
                float a2 = acc[mt][2] * s0, a3 = acc[mt][3] * s1;
                float rs0 = a0 + a1, rs1 = a2 + a3;
                int rr = mt * 16 + g, cc = h * 32 + nb + 2 * t;
                *(half2*)&At[rr * STRA + cc]       = __floats2half2_rn(a0, a1);
                *(half2*)&At[(rr + 8) * STRA + cc] = __floats2half2_rn(a2, a3);
                rs0 += __shfl_xor_sync(~0u, rs0, 1);
                rs0 += __shfl_xor_sync(~0u, rs0, 2);
                rs1 += __shfl_xor_sync(~0u, rs1, 1);
                rs1 += __shfl_xor_sync(~0u, rs1, 2);
                if (t == 0) {
                    atomicAdd(&ssm[rr], rs0);
                    atomicAdd(&ssm[rr + 8], rs1);
                }
            }
        }
        __syncthreads();

        // ---- GEMM2 accumulate over 64 n-rows (4 k-steps): all 8 warps ----
        {
            const unsigned short* Xu = (const unsigned short*)xs;
            const int db = 16 * w;
            #pragma unroll
            for (int s = 0; s < 4; s++) {
                uint32_t a[4][4];
                #pragma unroll
                for (int mt = 0; mt < 4; mt++)
                    LDSM4(a[mt], aAddr2 + mt * 2304 + s * 32);
                #pragma unroll
                for (int nt = 0; nt < 2; nt++) {
                    int dcol = db + 8 * nt + g;
                    int rh = (iter * 64 + 16 * s + 2 * t) * STRC + dcol;
                    uint32_t lo0 = Xu[rh],            hi0 = Xu[rh + STRC];
                    uint32_t lo1 = Xu[rh + 8 * STRC], hi1 = Xu[rh + 9 * STRC];
                    uint32_t bfr[2] = { lo0 | (hi0 << 16), lo1 | (hi1 << 16) };
                    #pragma unroll
                    for (int mt = 0; mt < 4; mt++) mma16(pc[mt][nt], a[mt], bfr);
                }
            }
        }
        __syncthreads();   // protect At before next iteration overwrites it
    }

    // ---- ONE partial store for the 128-row block ----
    {
        float* Pb = g_Pp + (size_t)(b * TILES + tile) * KK * DD;
        const int db = 16 * w;
        #pragma unroll
        for (int mt = 0; mt < 4; mt++)
            #pragma unroll
            for (int nt = 0; nt < 2; nt++) {
                int rr = mt * 16 + g, dd2 = db + 8 * nt + 2 * t;
                *(float2*)&Pb[rr * DD + dd2]       = make_float2(pc[mt][nt][0], pc[mt][nt][1]);
                *(float2*)&Pb[(rr + 8) * DD + dd2] = make_float2(pc[mt][nt][2], pc[mt][nt][3]);
            }
        if (tid < 64) g_sp[(b * TILES + tile) * KK + tid] = ssm[tid];
    }

    // ================= cross-CTA barrier (per b, 16 arrivals) =================
    __threadfence();
    __syncthreads();
    if (tid == 0) {
        atomicAdd(&g_arr[b], 1u);
        volatile unsigned int* va = &g_arr[b];
        while (*va < TILES) __nanosleep(64);
        __threadfence();
        unsigned int my = atomicAdd(&g_dep[b], 1u);
        if (my == TILES - 1) { g_arr[b] = 0u; g_dep[b] = 0u; }
    }
    __syncthreads();

    // ================= phase 2: CTA (b,tile) finalizes k = 4*tile + {0..3} ====
    // Warp w: k-quarter kq = w>>1, tile-half wsub = w&1 (8 tiles each, float4).
    {
        const int k0 = tile * 4;
        const int kq = w >> 1, wsub = w & 1;
        const int k = k0 + kq;
        float* ps = (float*)smc;   // reuse Cs region: 4k x 256 floats = 4KB
        const float4* P4 = (const float4*)g_Pp;
        float4 a = make_float4(0.f, 0.f, 0.f, 0.f);
        #pragma unroll
        for (int tt = wsub * 8; tt < wsub * 8 + 8; tt++) {
            float4 v = __ldcg(&P4[((size_t)(b * TILES + tt) * KK + k) * 32 + l]);
            a.x += v.x; a.y += v.y; a.z += v.z; a.w += v.w;
        }
        ((float4*)(ps + (kq * 2 + wsub) * 128))[l] = a;

        // s[k]: even warps; lane = tile index (<16)
        if (wsub == 0) {
            float sv = (l < TILES) ? __ldcg(&g_sp[(b * TILES + l) * KK + k]) : 0.f;
            #pragma unroll
            for (int o = 16; o; o >>= 1) sv += __shfl_xor_sync(~0u, sv, o);
            if (l == 0) red[kq] = sv;
        }
        __syncthreads();

        #pragma unroll
        for (int kk = 0; kk < 2; kk++) {
            const int kidx = (tid >> 7) + 2 * kk;   // warps 0-3 / 4-7 split
            const int d = tid & 127;
            float v = ps[kidx * 256 + d] + ps[kidx * 256 + 128 + d];
            v = fmaf(-red[kidx], cent[(k0 + kidx) * DD + d], v);
            float ssq = v * v;
            #pragma unroll
            for (int o = 16; o; o >>= 1) ssq += __shfl_xor_sync(~0u, ssq, o);
            if (l == 0) red[8 + kk * 8 + w] = ssq;
            __syncthreads();
            int gh = tid >> 7;
            float tot = (red[8 + kk * 8 + gh * 4]     + red[8 + kk * 8 + gh * 4 + 1]) +
                        (red[8 + kk * 8 + gh * 4 + 2] + red[8 + kk * 8 + gh * 4 + 3]);
            float sc = 0.125f * frsqrt(fmaxf(tot, 1e-24f));  // exact global norm = 8
            out[((size_t)b * KK + k0 + kidx) * DD + d] = v * sc;
        }
    }
}

// ---------------------------------------------------------------------------
extern "C" void kernel_launch(void* const* d_in, const int* in_sizes, int n_in,
                              void* d_out, int out_size) {
    (void)in_sizes; (void)n_in; (void)out_size;
    const float* x    = (const float*)d_in[0];
    const float* cent = (const float*)d_in[1];
    float* out        = (float*)d_out;

    cudaFuncSetAttribute(nv_main, cudaFuncAttributeMaxDynamicSharedMemorySize, SMEMB);
    nv_main<<<dim3(TILES, BB), 256, SMEMB>>>(x, cent, out);
}

// round 16
// speedup vs baseline: 1.2462x; 1.0022x over previous
#include <cuda_runtime.h>
#include <cuda_fp16.h>
#include <cstdint>
#include <math.h>

#define BB 8
#define NN 2048
#define DD 128
#define KK 64
#define ROWS 128    // rows per CTA
#define TILES 16    // NN / ROWS

// per-tile partials (fully rewritten every launch -> no zero kernel)
__device__ float g_Pp[BB * TILES * KK * DD];   // 4 MB (L2-resident)
__device__ float g_sp[BB * TILES * KK];
__device__ unsigned int g_arr[BB];
__device__ unsigned int g_dep[BB];

// half strides: all matrices 136 halves/row (68 words -> conflict-free ldmatrix)
#define STRC 136
#define STRA 136

// smem byte offsets
#define O_CS   0                        // 64*136*2  = 17408
#define O_XS   17408                    // 128*136*2 = 34816
#define O_AT   52224                    // 64*136*2  = 17408
#define O_CN2  69632                    // 64 floats
#define O_SSM  69888                    // 64 floats
#define O_RED  70144                    // 32 floats
#define SMEMB  70272

// ---- FFMA-only transcendentals (avoid the 0.5 op/cyc/SM MUFU pipe) ----
__device__ __forceinline__ float fexp(float x) {      // e^x, |x| small here
    float y = x * 1.4426950408889634f;
    float t = y + 12582912.f;
    int j = __float_as_int(t) << 23;
    float f = y - (t - 12582912.f);
    float p = 1.3333558e-3f;
    p = fmaf(p, f, 9.6181291e-3f);
    p = fmaf(p, f, 5.5504109e-2f);
    p = fmaf(p, f, 2.4022648e-1f);
    p = fmaf(p, f, 6.9314718e-1f);
    p = fmaf(p, f, 1.0f);
    return __int_as_float(__float_as_int(p) + j);
}
__device__ __forceinline__ float frsqrt(float s) {
    float h = __int_as_float(0x5f375a86 - (__float_as_int(s) >> 1));
    h = h * fmaf(-0.5f * s, h * h, 1.5f);
    h = h * fmaf(-0.5f * s, h * h, 1.5f);
    return h;
}
__device__ __forceinline__ float frcp(float s) {
    float r = __int_as_float(0x7ef311c3 - __float_as_int(s));
    r = r * fmaf(-s, r, 2.0f);
    r = r * fmaf(-s, r, 2.0f);
    return r;
}

__device__ __forceinline__ void mma16(float* d, const uint32_t* a, const uint32_t* b) {
    asm volatile(
        "mma.sync.aligned.m16n8k16.row.col.f32.f16.f16.f32 "
        "{%0,%1,%2,%3}, {%4,%5,%6,%7}, {%8,%9}, {%0,%1,%2,%3};"
        : "+f"(d[0]), "+f"(d[1]), "+f"(d[2]), "+f"(d[3])
        : "r"(a[0]), "r"(a[1]), "r"(a[2]), "r"(a[3]), "r"(b[0]), "r"(b[1]));
}
#define LDSM4(r, addr) \
    asm volatile("ldmatrix.sync.aligned.m8n8.x4.shared.b16 {%0,%1,%2,%3}, [%4];" \
        : "=r"((r)[0]), "=r"((r)[1]), "=r"((r)[2]), "=r"((r)[3]) : "r"(addr))

// ---------------------------------------------------------------------------
// Fused kernel: grid = (16 tiles, 8 b) = 128 CTAs x 512 threads (16 warps),
// 1 CTA/SM (128 <= 148, all co-resident, balanced, spin barrier safe).
// Single pass: GEMM1 over all 128 rows (warp w: n in [8w,8w+8)), softmax,
// GEMM2 over all 128 rows (warp w: d in [8w,8w+8)). ONE partial store.
// Phase 2: 4 k-columns per CTA, 4 warps per k.
// ---------------------------------------------------------------------------
__global__ void __launch_bounds__(512)
nv_main(const float* __restrict__ x, const float* __restrict__ cent,
        float* __restrict__ out) {
    extern __shared__ char smc[];
    half*  xs  = (half*)(smc + O_XS);
    half*  At  = (half*)(smc + O_AT);
    float* cn2 = (float*)(smc + O_CN2);
    float* ssm = (float*)(smc + O_SSM);
    float* red = (float*)(smc + O_RED);
    const uint32_t sb = (uint32_t)__cvta_generic_to_shared(smc);

    const int tid = threadIdx.x, w = tid >> 5, l = tid & 31;
    const int g = l >> 2, t = l & 3;           // mma groupID / thread-in-group
    const int b = blockIdx.y, tile = blockIdx.x;
    const int nb = w * 8;

    if (tid < 64) ssm[tid] = 0.f;

    // ---- phase A: convert C -> fp16 smem; load+norm 128 x rows (8/warp) ----
    {
        half* Cs = (half*)(smc + O_CS);
        const float4* c4 = (const float4*)cent;
        const float4* x4 = (const float4*)(x + ((size_t)b * NN + (size_t)tile * ROWS) * DD);

        float4 xv[8];
        #pragma unroll
        for (int i = 0; i < 8; i++) xv[i] = x4[(w * 8 + i) * 32 + l];

        #pragma unroll
        for (int i = tid; i < KK * DD / 4; i += 512) {
            float4 v = c4[i];
            int k = i >> 5, d4 = (i & 31) * 4;
            *(half2*)&Cs[k * STRC + d4]     = __floats2half2_rn(v.x, v.y);
            *(half2*)&Cs[k * STRC + d4 + 2] = __floats2half2_rn(v.z, v.w);
        }

        #pragma unroll
        for (int i = 0; i < 8; i++) {
            float4 v = xv[i];
            float ss = v.x * v.x + v.y * v.y + v.z * v.z + v.w * v.w;
            #pragma unroll
            for (int o = 16; o; o >>= 1) ss += __shfl_xor_sync(~0u, ss, o);
            float ri = frsqrt(fmaxf(ss, 1e-24f));
            int r = w * 8 + i;
            *(half2*)&xs[r * STRC + 4 * l]     = __floats2half2_rn(v.x * ri, v.y * ri);
            *(half2*)&xs[r * STRC + 4 * l + 2] = __floats2half2_rn(v.z * ri, v.w * ri);
        }
    }
    __syncthreads();

    // ---- cn2[k] = ||c_k||^2 from rounded halves ----
    if (tid < 128) {
        const half* Cs = (const half*)(smc + O_CS);
        int kc = tid >> 1, q = tid & 1;
        float s = 0.f;
        #pragma unroll
        for (int j = 0; j < 32; j++) {
            float2 f = __half22float2(*(const half2*)&Cs[kc * STRC + q * 64 + 2 * j]);
            s += f.x * f.x + f.y * f.y;
        }
        s += __shfl_xor_sync(~0u, s, 1);
        if (q == 0) cn2[kc] = s;
    }
    __syncthreads();

    // ---- GEMM1: S^T[k][n] = C * xn^T, ALL 128 n at once (warp w: [8w,8w+8)) ----
    const uint32_t aAddr1 = sb + O_CS + (uint32_t)((l & 15) * 272 + (l >> 4) * 16);
    const uint32_t aAddr2 = sb + O_AT + (uint32_t)((l & 15) * 272 + (l >> 4) * 16);
    {
        const uint32_t* Xw = (const uint32_t*)xs;
        float acc[4][4];
        #pragma unroll
        for (int mt = 0; mt < 4; mt++)
            #pragma unroll
            for (int q = 0; q < 4; q++) acc[mt][q] = 0.f;

        #pragma unroll
        for (int s = 0; s < 8; s++) {
            uint32_t a[4][4], bf[2];
            #pragma unroll
            for (int mt = 0; mt < 4; mt++)
                LDSM4(a[mt], aAddr1 + mt * 4352 + s * 32);
            int bb2 = (nb + g) * 68 + 8 * s + t;
            bf[0] = Xw[bb2];
            bf[1] = Xw[bb2 + 4];
            #pragma unroll
            for (int mt = 0; mt < 4; mt++) mma16(acc[mt], a[mt], bf);
        }

        // softmax per n-column over k=64 (args tiny -> no max shift)
        float s0 = 0.f, s1 = 0.f;
        #pragma unroll
        for (int mt = 0; mt < 4; mt++) {
            float cA = cn2[mt * 16 + g], cB = cn2[mt * 16 + g + 8];
            acc[mt][0] = fexp(fmaf(-2.f, acc[mt][0], cA));
            acc[mt][1] = fexp(fmaf(-2.f, acc[mt][1], cA));
            acc[mt][2] = fexp(fmaf(-2.f, acc[mt][2], cB));
            acc[mt][3] = fexp(fmaf(-2.f, acc[mt][3], cB));
            s0 += acc[mt][0] + acc[mt][2];
            s1 += acc[mt][1] + acc[mt][3];
        }
        #pragma unroll
        for (int o = 4; o <= 16; o <<= 1) {
            s0 += __shfl_xor_sync(~0u, s0, o);
            s1 += __shfl_xor_sync(~0u, s1, o);
        }
        s0 = frcp(s0);
        s1 = frcp(s1);

        // assign -> At[k][n] (fp16) + row sums -> ssm
        #pragma unroll
        for (int mt = 0; mt < 4; mt++) {
            float a0 = acc[mt][0] * s0, a1 = acc[mt][1] * s1;
            float a2 = acc[mt][2] * s0, a3 = acc[mt][3] * s1;
            float rs0 = a0 + a1, rs1 = a2 + a3;
            int rr = mt * 16 + g, cc = nb + 2 * t;
            *(half2*)&At[rr * STRA + cc]       = __floats2half2_rn(a0, a1);
            *(half2*)&At[(rr + 8) * STRA + cc] = __floats2half2_rn(a2, a3);
            rs0 += __shfl_xor_sync(~0u, rs0, 1);
            rs0 += __shfl_xor_sync(~0u, rs0, 2);
            rs1 += __shfl_xor_sync(~0u, rs1, 1);
            rs1 += __shfl_xor_sync(~0u, rs1, 2);
            if (t == 0) {
                atomicAdd(&ssm[rr], rs0);
                atomicAdd(&ssm[rr + 8], rs1);
            }
        }
    }
    __syncthreads();

    // ---- GEMM2: P[k][d] = At[k][n] * Xn[n][d] over 128 n; warp w: d [8w,8w+8) ----
    float pc[4][4];
    #pragma unroll
    for (int mt = 0; mt < 4; mt++)
        #pragma unroll
        for (int q = 0; q < 4; q++) pc[mt][q] = 0.f;
    {
        const unsigned short* Xu = (const unsigned short*)xs;
        #pragma unroll
        for (int s = 0; s < 8; s++) {
            uint32_t a[4][4];
            #pragma unroll
            for (int mt = 0; mt < 4; mt++)
                LDSM4(a[mt], aAddr2 + mt * 4352 + s * 32);
            int dcol = nb + g;
            int rh = (16 * s + 2 * t) * STRC + dcol;
            uint32_t lo0 = Xu[rh],            hi0 = Xu[rh + STRC];
            uint32_t lo1 = Xu[rh + 8 * STRC], hi1 = Xu[rh + 9 * STRC];
            uint32_t bfr[2] = { lo0 | (hi0 << 16), lo1 | (hi1 << 16) };
            #pragma unroll
            for (int mt = 0; mt < 4; mt++) mma16(pc[mt], a[mt], bfr);
        }
    }

    // ---- ONE partial store (warp w: d cols [8w, 8w+8)) ----
    {
        float* Pb = g_Pp + (size_t)(b * TILES + tile) * KK * DD;
        #pragma unroll
        for (int mt = 0; mt < 4; mt++) {
            int rr = mt * 16 + g, dd2 = nb + 2 * t;
            *(float2*)&Pb[rr * DD + dd2]       = make_float2(pc[mt][0], pc[mt][1]);
            *(float2*)&Pb[(rr + 8) * DD + dd2] = make_float2(pc[mt][2], pc[mt][3]);
        }
        if (tid < 64) g_sp[(b * TILES + tile) * KK + tid] = ssm[tid];
    }

    // ================= cross-CTA barrier (per b, 16 arrivals) =================
    __threadfence();
    __syncthreads();
    if (tid == 0) {
        atomicAdd(&g_arr[b], 1u);
        volatile unsigned int* va = &g_arr[b];
        while (*va < TILES) __nanosleep(64);
        __threadfence();
        unsigned int my = atomicAdd(&g_dep[b], 1u);
        if (my == TILES - 1) { g_arr[b] = 0u; g_dep[b] = 0u; }
    }
    __syncthreads();

    // ================= phase 2: CTA (b,tile) finalizes k = 4*tile + {0..3} ====
    // Warp w: k-quarter kq = w>>2, tile-quarter wsub = w&3 (4 tiles each).
    {
        const int k0 = tile * 4;
        const int kq = w >> 2, wsub = w & 3;
        const int k = k0 + kq;
        float* ps = (float*)smc;   // reuse Cs region: 4k x 4w x 128 = 8KB
        const float4* P4 = (const float4*)g_Pp;
        float4 a = make_float4(0.f, 0.f, 0.f, 0.f);
        #pragma unroll
        for (int tt = wsub * 4; tt < wsub * 4 + 4; tt++) {
            float4 v = __ldcg(&P4[((size_t)(b * TILES + tt) * KK + k) * 32 + l]);
            a.x += v.x; a.y += v.y; a.z += v.z; a.w += v.w;
        }
        ((float4*)(ps + (kq * 4 + wsub) * 128))[l] = a;

        // s[k]: warps with wsub==0; lane = tile index (<16)
        if (wsub == 0) {
            float sv = (l < TILES) ? __ldcg(&g_sp[(b * TILES + l) * KK + k]) : 0.f;
            #pragma unroll
            for (int o = 8; o; o >>= 1) sv += __shfl_xor_sync(~0u, sv, o);
            if (l == 0) red[kq] = sv;
        }
        __syncthreads();

        // combine: thread = (kidx, d); kidx = tid>>7 (warp-uniform), d = tid&127
        const int kidx = tid >> 7, d = tid & 127;
        float v = (ps[kidx * 512 + d] + ps[kidx * 512 + 128 + d]) +
                  (ps[kidx * 512 + 256 + d] + ps[kidx * 512 + 384 + d]);
        v = fmaf(-red[kidx], cent[(k0 + kidx) * DD + d], v);
        float ssq = v * v;
        #pragma unroll
        for (int o = 16; o; o >>= 1) ssq += __shfl_xor_sync(~0u, ssq, o);
        if (l == 0) red[8 + w] = ssq;
        __syncthreads();
        float tot = (red[8 + kidx * 4] + red[9 + kidx * 4]) +
                    (red[10 + kidx * 4] + red[11 + kidx * 4]);
        float sc = 0.125f * frsqrt(fmaxf(tot, 1e-24f));   // exact global norm = 8
        out[((size_t)b * KK + k0 + kidx) * DD + d] = v * sc;
    }
}

// ---------------------------------------------------------------------------
extern "C" void kernel_launch(void* const* d_in, const int* in_sizes, int n_in,
                              void* d_out, int out_size) {
    (void)in_sizes; (void)n_in; (void)out_size;
    const float* x    = (const float*)d_in[0];
    const float* cent = (const float*)d_in[1];
    float* out        = (float*)d_out;

    cudaFuncSetAttribute(nv_main, cudaFuncAttributeMaxDynamicSharedMemorySize, SMEMB);
    nv_main<<<dim3(TILES, BB), 512, SMEMB>>>(x, cent, out);
}